// round 14
// baseline (speedup 1.0000x reference)
#include <cuda_runtime.h>
#include <math.h>
#include <stdint.h>

// Problem constants
#define BATCH 32
#define CDIM  256
#define HW    1024            // 32*32
#define NPOS  32768           // BATCH*HW
#define KCODE 1024
#define TOTAL 8388608         // BATCH*CDIM*HW

typedef unsigned long long ull;

// Scratch (device globals; no allocation allowed)
__device__ int           g_idx[NPOS];
__device__ float         g_wsq[KCODE];
__device__ float         g_zsq[NPOS];
__device__ unsigned int  g_counts[KCODE];
__device__ float         g_partial[1024];
__device__ __align__(16) float          g_zt[NPOS * CDIM];       // z transposed [pos][c]
__device__ __align__(16) unsigned short g_zbf[NPOS * CDIM];      // bf16 z [pos][c]
__device__ __align__(16) unsigned short g_wbf[KCODE * CDIM];     // bf16 w [k][c]
__device__ __align__(16) unsigned short g_scores[NPOS * KCODE];  // bf16 approx scores

#define MARGIN 0.01f

// pack two fp32 -> bf16x2 (lo in bits[15:0])
#define CVTB(d, hi, lo) \
    asm("cvt.rn.bf16x2.f32 %0, %1, %2;" : "=r"(d) : "f"(hi), "f"(lo))

#define CP_ASYNC16(dst_u32, src_ptr) \
    asm volatile("cp.async.ca.shared.global [%0], [%1], 16;" :: "r"(dst_u32), "l"(src_ptr))
#define CP_COMMIT() asm volatile("cp.async.commit_group;")
#define CP_WAIT0()  asm volatile("cp.async.wait_group 0;")

__device__ __forceinline__ uint32_t smem_to_u32(const void* p) {
    uint32_t a;
    asm("{ .reg .u64 t; cvta.to.shared.u64 t, %1; cvt.u32.u64 %0, t; }" : "=r"(a) : "l"(p));
    return a;
}

// sm80-class tensor ops (available on base sm_103 target)
#define LDSM4(r, addr) \
    asm volatile("ldmatrix.sync.aligned.m8n8.x4.shared.b16 {%0,%1,%2,%3}, [%4];" \
        : "=r"((r)[0]), "=r"((r)[1]), "=r"((r)[2]), "=r"((r)[3]) : "r"(addr))
#define MMA16816(d, a, b) \
    asm volatile("mma.sync.aligned.m16n8k16.row.col.f32.bf16.bf16.f32 " \
        "{%0,%1,%2,%3}, {%4,%5,%6,%7}, {%8,%9}, {%0,%1,%2,%3};" \
        : "+f"((d)[0]), "+f"((d)[1]), "+f"((d)[2]), "+f"((d)[3]) \
        : "r"((a)[0]), "r"((a)[1]), "r"((a)[2]), "r"((a)[3]), \
          "r"((b)[0]), "r"((b)[1]))

// ---------------------------------------------------------------------------
// Kernel W: wsq + zero counts + w -> bf16
// ---------------------------------------------------------------------------
__global__ __launch_bounds__(256) void k_wsq(const float* __restrict__ w) {
    const int t = threadIdx.x;
    if (blockIdx.x < 4) g_counts[blockIdx.x * 256 + t] = 0u;
    const int gid = blockIdx.x * 256 + t;
    {
        const float* src = w + gid * 8;
        float4 a = *(const float4*)src;
        float4 b = *(const float4*)(src + 4);
        uint32_t q0, q1, q2, q3;
        CVTB(q0, a.y, a.x); CVTB(q1, a.w, a.z);
        CVTB(q2, b.y, b.x); CVTB(q3, b.w, b.z);
        ((uint4*)g_wbf)[gid] = make_uint4(q0, q1, q2, q3);
    }
    int warp = gid >> 5;
    int lane = t & 31;
    const float* row = w + (size_t)warp * CDIM;
    float s = 0.f;
    #pragma unroll
    for (int j = 0; j < CDIM / 32; ++j) {
        float v = row[lane + j * 32];
        s = fmaf(v, v, s);
    }
    #pragma unroll
    for (int off = 16; off > 0; off >>= 1)
        s += __shfl_down_sync(0xFFFFFFFFu, s, off);
    if (lane == 0) g_wsq[warp] = s;
}

// ---------------------------------------------------------------------------
// Kernel P: transpose z -> z_t (fp32) + zbf (bf16) + zsq. Block = 32 positions.
// ---------------------------------------------------------------------------
__global__ __launch_bounds__(256) void k_prep(const float* __restrict__ z) {
    __shared__ float sm[256][33];
    const int t   = threadIdx.x;
    const int n0  = blockIdx.x * 32;
    const int b   = n0 >> 10;
    const int hw0 = n0 & 1023;
    const float* zb = z + (size_t)b * (CDIM * HW) + hw0;

    #pragma unroll 8
    for (int it = 0; it < 32; ++it) {
        int idx = it * 256 + t;
        int c = idx >> 5, hwi = idx & 31;
        sm[c][hwi] = zb[(size_t)c * HW + hwi];
    }
    __syncthreads();

    // zsq (warp per 4 positions)
    {
        const int wrp = t >> 5, lane = t & 31;
        for (int r = 0; r < 4; ++r) {
            const int hwi = wrp * 4 + r;
            float acc = 0.f;
            #pragma unroll
            for (int i = 0; i < 8; ++i) {
                float a = sm[32 * i + lane][hwi];
                acc = __fadd_rn(acc, __fmul_rn(a, a));
            }
            #pragma unroll
            for (int off = 16; off > 0; off >>= 1)
                acc = __fadd_rn(acc, __shfl_down_sync(0xFFFFFFFFu, acc, off));
            if (lane == 0) g_zsq[n0 + hwi] = acc;
        }
    }

    // transpose writes: 8 threads per position, 32 channels each
    {
        const int p  = t >> 3;
        const int c0 = (t & 7) * 32;
        float* dst = g_zt + (size_t)(n0 + p) * CDIM + c0;
        #pragma unroll
        for (int i = 0; i < 8; ++i) {
            float4 v = make_float4(sm[c0 + 4*i][p], sm[c0 + 4*i + 1][p],
                                   sm[c0 + 4*i + 2][p], sm[c0 + 4*i + 3][p]);
            *(float4*)(dst + 4*i) = v;
        }
        uint4* bd = (uint4*)(g_zbf + (size_t)(n0 + p) * CDIM + c0);
        #pragma unroll
        for (int i = 0; i < 4; ++i) {
            uint32_t q0, q1, q2, q3;
            CVTB(q0, sm[c0 + 8*i + 1][p], sm[c0 + 8*i + 0][p]);
            CVTB(q1, sm[c0 + 8*i + 3][p], sm[c0 + 8*i + 2][p]);
            CVTB(q2, sm[c0 + 8*i + 5][p], sm[c0 + 8*i + 4][p]);
            CVTB(q3, sm[c0 + 8*i + 7][p], sm[c0 + 8*i + 6][p]);
            bd[i] = make_uint4(q0, q1, q2, q3);
        }
    }
}

// ---------------------------------------------------------------------------
// Kernel G: bf16 warp-MMA GEMM -> approx scores s~ = wsq - 2*D (bf16).
// Grid (8 kblocks, 256 posblocks); block = 128 pos x 128 codes, K=256 in
// 8 double-buffered 32-c chunks. 8 warps of 64 pos x 32 codes.
// smem pitch 80B -> ldmatrix rows hit disjoint bank quads (conflict-free).
// ---------------------------------------------------------------------------
#define ZPITCHB 80      // bytes per smem row (32 bf16 + 8 pad)
#define SCPITCH 136     // bf16 elements per score row (128 + 8 pad)

__global__ __launch_bounds__(256, 2) void k_gemm() {
    __shared__ __align__(16) unsigned short smbuf[20480];  // 40 KB

    const int t    = threadIdx.x;
    const int lane = t & 31;
    const int wid  = t >> 5;
    const int py   = wid >> 2;          // pos half (0..1)
    const int kb   = (wid & 3) * 32;    // warp code base within 128

    const int pos0 = blockIdx.y * 128;
    const int K0   = blockIdx.x * 128;

    const uint32_t sbase = smem_to_u32(smbuf);
    // layout: z buf b at byte b*10240; w buf b at 20480 + b*10240

    // staging: thread -> row t>>1, two 16B segments
    const int srow = t >> 1;
    const int sseg = (t & 1) * 32;      // byte offset of first segment
    const char* zsrc = (const char*)(g_zbf + (size_t)(pos0 + srow) * 256) + sseg;
    const char* wsrc = (const char*)(g_wbf + (size_t)(K0 + srow) * 256) + sseg;
    const uint32_t zdst = sbase + srow * ZPITCHB + sseg;
    const uint32_t wdst = sbase + 20480u + srow * ZPITCHB + sseg;

    // ldmatrix lane addressing
    const int lrow16 = lane & 15;              // A row within 16
    const int lcol8  = (lane >> 4) << 3;       // A col group (elements)
    const int q      = lane >> 3;
    const int brow   = ((q >> 1) << 3) + (lane & 7);   // B n row within 16
    const int bk8    = (q & 1) << 3;                   // B k group (elements)

    float acc[4][4][4];
    #pragma unroll
    for (int f = 0; f < 4; ++f)
        #pragma unroll
        for (int n = 0; n < 4; ++n)
            #pragma unroll
            for (int e = 0; e < 4; ++e) acc[f][n][e] = 0.f;

    // prefetch chunk 0 into buf 0
    CP_ASYNC16(zdst, zsrc);
    CP_ASYNC16(zdst + 16, zsrc + 16);
    CP_ASYNC16(wdst, wsrc);
    CP_ASYNC16(wdst + 16, wsrc + 16);
    CP_COMMIT();
    CP_WAIT0();
    __syncthreads();

    int p = 0;
    for (int ct = 0; ct < 8; ++ct) {
        if (ct < 7) {
            const uint32_t nb = (uint32_t)(p ^ 1) * 10240u;
            const int coff = (ct + 1) * 64;   // 32 c = 64 bytes
            CP_ASYNC16(zdst + nb, zsrc + coff);
            CP_ASYNC16(zdst + nb + 16, zsrc + coff + 16);
            CP_ASYNC16(wdst + nb, wsrc + coff);
            CP_ASYNC16(wdst + nb + 16, wsrc + coff + 16);
            CP_COMMIT();
        }
        const uint32_t zb = sbase + (uint32_t)p * 10240u;
        const uint32_t wb = sbase + 20480u + (uint32_t)p * 10240u;
        #pragma unroll
        for (int s = 0; s < 2; ++s) {
            uint32_t af[4][4];
            #pragma unroll
            for (int f = 0; f < 4; ++f) {
                uint32_t addr = zb + (uint32_t)(py * 64 + f * 16 + lrow16) * ZPITCHB
                              + (uint32_t)(s * 16 + lcol8) * 2u;
                LDSM4(af[f], addr);
            }
            uint32_t bf[4][2];
            #pragma unroll
            for (int nb2 = 0; nb2 < 2; ++nb2) {
                uint32_t r[4];
                uint32_t addr = wb + (uint32_t)(kb + nb2 * 16 + brow) * ZPITCHB
                              + (uint32_t)(s * 16 + bk8) * 2u;
                LDSM4(r, addr);
                bf[nb2 * 2][0] = r[0]; bf[nb2 * 2][1] = r[1];
                bf[nb2 * 2 + 1][0] = r[2]; bf[nb2 * 2 + 1][1] = r[3];
            }
            #pragma unroll
            for (int f = 0; f < 4; ++f)
                #pragma unroll
                for (int n = 0; n < 4; ++n)
                    MMA16816(acc[f][n], af[f], bf[n]);
        }
        if (ct < 7) {
            CP_WAIT0();
            __syncthreads();
            p ^= 1;
        }
    }
    __syncthreads();   // all warps done reading smem before reuse

    // epilogue: s~ = wsq - 2*D, packed bf16x2 into smem score tile
    const int lr4 = lane >> 2;
    const int lc2 = (lane & 3) * 2;
    #pragma unroll
    for (int f = 0; f < 4; ++f) {
        const int r0 = py * 64 + f * 16 + lr4;
        #pragma unroll
        for (int n = 0; n < 4; ++n) {
            const int col = kb + n * 8 + lc2;
            float2 wq = *(const float2*)(g_wsq + K0 + col);
            uint32_t pk;
            float s0 = fmaf(-2.0f, acc[f][n][0], wq.x);
            float s1 = fmaf(-2.0f, acc[f][n][1], wq.y);
            CVTB(pk, s1, s0);
            *(uint32_t*)((char*)smbuf + (size_t)(r0 * SCPITCH + col) * 2) = pk;
            float s2 = fmaf(-2.0f, acc[f][n][2], wq.x);
            float s3 = fmaf(-2.0f, acc[f][n][3], wq.y);
            CVTB(pk, s3, s2);
            *(uint32_t*)((char*)smbuf + (size_t)((r0 + 8) * SCPITCH + col) * 2) = pk;
        }
    }
    __syncthreads();

    // coalesced copy-out: 128 rows x 256 B
    #pragma unroll
    for (int i = 0; i < 8; ++i) {
        int idx = t + i * 256;
        int row = idx >> 4, seg = idx & 15;
        uint4 v = *(const uint4*)((const char*)smbuf + (size_t)row * (SCPITCH * 2) + seg * 16);
        *(uint4*)((char*)(g_scores + (size_t)(pos0 + row) * 1024 + K0) + seg * 16) = v;
    }
}

// ---------------------------------------------------------------------------
// Kernel S: per-position scan: min of approx scores, flag within MARGIN,
// exact fp32-chain rescore of flagged candidates, argmin with lowest-index tie.
// ---------------------------------------------------------------------------
__device__ __forceinline__ float chain256(const float* __restrict__ zr,
                                          const float* __restrict__ wr) {
    float m = 0.f;
    #pragma unroll 16
    for (int j = 0; j < 64; ++j) {
        float4 a = *(const float4*)(zr + 4 * j);
        float4 b = *(const float4*)(wr + 4 * j);
        m = fmaf(a.x, b.x, m);
        m = fmaf(a.y, b.y, m);
        m = fmaf(a.z, b.z, m);
        m = fmaf(a.w, b.w, m);
    }
    return m;
}

__global__ __launch_bounds__(256) void k_scan(const float* __restrict__ w) {
    const int t = threadIdx.x;
    const int wid = t >> 5, lane = t & 31;

    for (int pp = 0; pp < 4; ++pp) {
        const int pos = blockIdx.x * 32 + wid * 4 + pp;
        const uint4* srow = (const uint4*)(g_scores) + (size_t)pos * 128 + lane * 4;
        uint4 v[4];
        #pragma unroll
        for (int i = 0; i < 4; ++i) v[i] = srow[i];

        float mn = 3.4e38f;
        #pragma unroll
        for (int i = 0; i < 4; ++i) {
            const uint32_t* u = (const uint32_t*)&v[i];
            #pragma unroll
            for (int e = 0; e < 4; ++e) {
                float f0 = __uint_as_float(u[e] << 16);
                float f1 = __uint_as_float(u[e] & 0xFFFF0000u);
                mn = fminf(mn, fminf(f0, f1));
            }
        }
        #pragma unroll
        for (int off = 16; off > 0; off >>= 1)
            mn = fminf(mn, __shfl_xor_sync(0xFFFFFFFFu, mn, off));
        const float thr = mn + MARGIN;
        const float zsq = g_zsq[pos];

        ull best = ~0ull;
        #pragma unroll
        for (int i = 0; i < 4; ++i) {
            const uint32_t* u = (const uint32_t*)&v[i];
            #pragma unroll
            for (int e = 0; e < 4; ++e) {
                const int kk = lane * 32 + i * 8 + e * 2;
                float f0 = __uint_as_float(u[e] << 16);
                float f1 = __uint_as_float(u[e] & 0xFFFF0000u);
                if (f0 <= thr) {
                    float m = chain256(g_zt + (size_t)pos * CDIM, w + (size_t)kk * CDIM);
                    float sc = __fadd_rn(fmaf(-2.0f, m, zsq), g_wsq[kk]);
                    unsigned uu = __float_as_uint(sc);
                    uu = (uu & 0x80000000u) ? ~uu : (uu | 0x80000000u);
                    ull e64 = ((ull)uu << 32) | (unsigned)kk;
                    if (e64 < best) best = e64;
                }
                if (f1 <= thr) {
                    const int k1 = kk + 1;
                    float m = chain256(g_zt + (size_t)pos * CDIM, w + (size_t)k1 * CDIM);
                    float sc = __fadd_rn(fmaf(-2.0f, m, zsq), g_wsq[k1]);
                    unsigned uu = __float_as_uint(sc);
                    uu = (uu & 0x80000000u) ? ~uu : (uu | 0x80000000u);
                    ull e64 = ((ull)uu << 32) | (unsigned)k1;
                    if (e64 < best) best = e64;
                }
            }
        }
        #pragma unroll
        for (int off = 16; off > 0; off >>= 1) {
            ull o = __shfl_xor_sync(0xFFFFFFFFu, best, off);
            if (o < best) best = o;
        }
        if (lane == 0) {
            int idx = (int)(best & 0xFFFFFFFFull);
            g_idx[pos] = idx;
            atomicAdd(&g_counts[idx], 1u);
        }
    }
}

// ---------------------------------------------------------------------------
// Kernel B: gather-transpose quantize (unchanged from R12).
// ---------------------------------------------------------------------------
#define QPITCH 257
__global__ __launch_bounds__(256) void k_quant(const float* __restrict__ z,
                                               const float* __restrict__ w,
                                               float* __restrict__ out) {
    __shared__ int   sidx[32];
    __shared__ float qs[32 * QPITCH];
    __shared__ float sm[256];

    const int t  = threadIdx.x;
    const int n0 = blockIdx.x * 32;
    const int b  = n0 >> 10;
    const int hw0 = n0 & 1023;

    if (t < 32) sidx[t] = g_idx[n0 + t];
    __syncthreads();

    {
        const int p  = t >> 3;
        const int cq = t & 7;
        const float* row = w + (size_t)sidx[p] * CDIM;
        #pragma unroll
        for (int i = 0; i < 8; ++i) {
            const int c4 = (i * 8 + cq) * 4;
            float4 v = *(const float4*)(row + c4);
            float* dst = &qs[p * QPITCH + c4];
            dst[0] = v.x; dst[1] = v.y; dst[2] = v.z; dst[3] = v.w;
        }
    }
    __syncthreads();

    const float* zb = z + (size_t)b * (CDIM * HW) + hw0;
    float* ob = out + (size_t)b * (CDIM * HW) + hw0;
    const int hw4 = (t & 7) * 4;
    float local = 0.f;
    #pragma unroll
    for (int it = 0; it < 8; ++it) {
        const int c = it * 32 + (t >> 3);
        float4 zz = *(const float4*)(zb + (size_t)c * HW + hw4);
        float q0 = qs[(hw4 + 0) * QPITCH + c];
        float q1 = qs[(hw4 + 1) * QPITCH + c];
        float q2 = qs[(hw4 + 2) * QPITCH + c];
        float q3 = qs[(hw4 + 3) * QPITCH + c];
        float4 o;
        float d;
        d = __fadd_rn(q0, -zz.x); o.x = __fadd_rn(zz.x, d); local = fmaf(d, d, local);
        d = __fadd_rn(q1, -zz.y); o.y = __fadd_rn(zz.y, d); local = fmaf(d, d, local);
        d = __fadd_rn(q2, -zz.z); o.z = __fadd_rn(zz.z, d); local = fmaf(d, d, local);
        d = __fadd_rn(q3, -zz.w); o.w = __fadd_rn(zz.w, d); local = fmaf(d, d, local);
        *(float4*)(ob + (size_t)c * HW + hw4) = o;
    }
    sm[t] = local;
    __syncthreads();
    for (int s = 128; s > 0; s >>= 1) {
        if (t < s) sm[t] += sm[t + s];
        __syncthreads();
    }
    if (t == 0) g_partial[blockIdx.x] = sm[0];
}

// ---------------------------------------------------------------------------
__global__ __launch_bounds__(1024) void k_final(float* __restrict__ out) {
    __shared__ float sm[1024];
    const int t = threadIdx.x;

    sm[t] = g_partial[t];
    __syncthreads();
    for (int s = 512; s > 0; s >>= 1) {
        if (t < s) sm[t] += sm[t + s];
        __syncthreads();
    }
    if (t == 0) {
        float m = sm[0] / (float)TOTAL;
        out[TOTAL] = m + 0.25f * m;      // q_latent + COMMITMENT_COST * e_latent
    }
    __syncthreads();

    float p = (float)g_counts[t] * (1.0f / (float)NPOS);
    sm[t] = p * logf(p + 1e-10f);
    __syncthreads();
    for (int s = 512; s > 0; s >>= 1) {
        if (t < s) sm[t] += sm[t + s];
        __syncthreads();
    }
    if (t == 0) out[TOTAL + 1] = expf(-sm[0]);
}

// ---------------------------------------------------------------------------
extern "C" void kernel_launch(void* const* d_in, const int* in_sizes, int n_in,
                              void* d_out, int out_size) {
    const float* z = (const float*)d_in[0];
    const float* w = (const float*)d_in[1];
    float* out = (float*)d_out;

    k_wsq<<<128, 256>>>(w);
    k_prep<<<NPOS / 32, 256>>>(z);
    k_gemm<<<dim3(8, 256), 256>>>();
    k_scan<<<NPOS / 32, 256>>>(w);
    k_quant<<<NPOS / 32, 256>>>(z, w, out);
    k_final<<<1, 1024>>>(out);
}

// round 15
// speedup vs baseline: 2.6463x; 2.6463x over previous
#include <cuda_runtime.h>
#include <math.h>
#include <stdint.h>

// Problem constants
#define BATCH 32
#define CDIM  256
#define HW    1024            // 32*32
#define NPOS  32768           // BATCH*HW
#define KCODE 1024
#define TOTAL 8388608         // BATCH*CDIM*HW

typedef unsigned long long ull;

#define CAND_CAP (1u << 20)

// Scratch (device globals; no allocation allowed)
__device__ float         g_wsq[KCODE];
__device__ float         g_zsq[NPOS];
__device__ unsigned int  g_counts[KCODE];
__device__ float         g_partial[1024];
__device__ __align__(16) float          g_zt[NPOS * CDIM];       // z transposed [pos][c]
__device__ __align__(16) unsigned short g_zbf[NPOS * CDIM];      // bf16 z [pos][c]
__device__ __align__(16) unsigned short g_wbf[KCODE * CDIM];     // bf16 w [k][c]
__device__ __align__(16) unsigned short g_scores[NPOS * KCODE];  // bf16 approx scores
__device__ unsigned int  g_ncand;
__device__ __align__(8) ull g_best[NPOS];
__device__ unsigned int  g_cand[CAND_CAP];

#define MARGIN 0.01f

// pack two fp32 -> bf16x2 (lo in bits[15:0])
#define CVTB(d, hi, lo) \
    asm("cvt.rn.bf16x2.f32 %0, %1, %2;" : "=r"(d) : "f"(hi), "f"(lo))

#define CP_ASYNC16(dst_u32, src_ptr) \
    asm volatile("cp.async.ca.shared.global [%0], [%1], 16;" :: "r"(dst_u32), "l"(src_ptr))
#define CP_COMMIT() asm volatile("cp.async.commit_group;")
#define CP_WAIT0()  asm volatile("cp.async.wait_group 0;")

__device__ __forceinline__ uint32_t smem_to_u32(const void* p) {
    uint32_t a;
    asm("{ .reg .u64 t; cvta.to.shared.u64 t, %1; cvt.u32.u64 %0, t; }" : "=r"(a) : "l"(p));
    return a;
}

// sm80-class tensor ops (available on base sm_103 target)
#define LDSM4(r, addr) \
    asm volatile("ldmatrix.sync.aligned.m8n8.x4.shared.b16 {%0,%1,%2,%3}, [%4];" \
        : "=r"((r)[0]), "=r"((r)[1]), "=r"((r)[2]), "=r"((r)[3]) : "r"(addr))
#define MMA16816(d, a, b) \
    asm volatile("mma.sync.aligned.m16n8k16.row.col.f32.bf16.bf16.f32 " \
        "{%0,%1,%2,%3}, {%4,%5,%6,%7}, {%8,%9}, {%0,%1,%2,%3};" \
        : "+f"((d)[0]), "+f"((d)[1]), "+f"((d)[2]), "+f"((d)[3]) \
        : "r"((a)[0]), "r"((a)[1]), "r"((a)[2]), "r"((a)[3]), \
          "r"((b)[0]), "r"((b)[1]))

// ---------------------------------------------------------------------------
// Kernel W: wsq + zero counts + zero cand count + w -> bf16
// ---------------------------------------------------------------------------
__global__ __launch_bounds__(256) void k_wsq(const float* __restrict__ w) {
    const int t = threadIdx.x;
    if (blockIdx.x < 4) g_counts[blockIdx.x * 256 + t] = 0u;
    if (blockIdx.x == 0 && t == 0) g_ncand = 0u;
    const int gid = blockIdx.x * 256 + t;
    {
        const float* src = w + gid * 8;
        float4 a = *(const float4*)src;
        float4 b = *(const float4*)(src + 4);
        uint32_t q0, q1, q2, q3;
        CVTB(q0, a.y, a.x); CVTB(q1, a.w, a.z);
        CVTB(q2, b.y, b.x); CVTB(q3, b.w, b.z);
        ((uint4*)g_wbf)[gid] = make_uint4(q0, q1, q2, q3);
    }
    int warp = gid >> 5;
    int lane = t & 31;
    const float* row = w + (size_t)warp * CDIM;
    float s = 0.f;
    #pragma unroll
    for (int j = 0; j < CDIM / 32; ++j) {
        float v = row[lane + j * 32];
        s = fmaf(v, v, s);
    }
    #pragma unroll
    for (int off = 16; off > 0; off >>= 1)
        s += __shfl_down_sync(0xFFFFFFFFu, s, off);
    if (lane == 0) g_wsq[warp] = s;
}

// ---------------------------------------------------------------------------
// Kernel P: transpose z -> z_t (fp32) + zbf (bf16) + zsq. Block = 32 positions.
// ---------------------------------------------------------------------------
__global__ __launch_bounds__(256) void k_prep(const float* __restrict__ z) {
    __shared__ float sm[256][33];
    const int t   = threadIdx.x;
    const int n0  = blockIdx.x * 32;
    const int b   = n0 >> 10;
    const int hw0 = n0 & 1023;
    const float* zb = z + (size_t)b * (CDIM * HW) + hw0;

    #pragma unroll 8
    for (int it = 0; it < 32; ++it) {
        int idx = it * 256 + t;
        int c = idx >> 5, hwi = idx & 31;
        sm[c][hwi] = zb[(size_t)c * HW + hwi];
    }
    __syncthreads();

    // zsq (warp per 4 positions)
    {
        const int wrp = t >> 5, lane = t & 31;
        for (int r = 0; r < 4; ++r) {
            const int hwi = wrp * 4 + r;
            float acc = 0.f;
            #pragma unroll
            for (int i = 0; i < 8; ++i) {
                float a = sm[32 * i + lane][hwi];
                acc = __fadd_rn(acc, __fmul_rn(a, a));
            }
            #pragma unroll
            for (int off = 16; off > 0; off >>= 1)
                acc = __fadd_rn(acc, __shfl_down_sync(0xFFFFFFFFu, acc, off));
            if (lane == 0) g_zsq[n0 + hwi] = acc;
        }
    }

    // transpose writes: 8 threads per position, 32 channels each
    {
        const int p  = t >> 3;
        const int c0 = (t & 7) * 32;
        float* dst = g_zt + (size_t)(n0 + p) * CDIM + c0;
        #pragma unroll
        for (int i = 0; i < 8; ++i) {
            float4 v = make_float4(sm[c0 + 4*i][p], sm[c0 + 4*i + 1][p],
                                   sm[c0 + 4*i + 2][p], sm[c0 + 4*i + 3][p]);
            *(float4*)(dst + 4*i) = v;
        }
        uint4* bd = (uint4*)(g_zbf + (size_t)(n0 + p) * CDIM + c0);
        #pragma unroll
        for (int i = 0; i < 4; ++i) {
            uint32_t q0, q1, q2, q3;
            CVTB(q0, sm[c0 + 8*i + 1][p], sm[c0 + 8*i + 0][p]);
            CVTB(q1, sm[c0 + 8*i + 3][p], sm[c0 + 8*i + 2][p]);
            CVTB(q2, sm[c0 + 8*i + 5][p], sm[c0 + 8*i + 4][p]);
            CVTB(q3, sm[c0 + 8*i + 7][p], sm[c0 + 8*i + 6][p]);
            bd[i] = make_uint4(q0, q1, q2, q3);
        }
    }
}

// ---------------------------------------------------------------------------
// Kernel G: bf16 warp-MMA GEMM -> approx scores s~ = wsq - 2*D (bf16).
// (unchanged from R14 — correct, ~90 us; next optimization target)
// ---------------------------------------------------------------------------
#define ZPITCHB 80      // bytes per smem row (32 bf16 + 8 pad)
#define SCPITCH 136     // bf16 elements per score row (128 + 8 pad)

__global__ __launch_bounds__(256, 2) void k_gemm() {
    __shared__ __align__(16) unsigned short smbuf[20480];  // 40 KB

    const int t    = threadIdx.x;
    const int lane = t & 31;
    const int wid  = t >> 5;
    const int py   = wid >> 2;          // pos half (0..1)
    const int kb   = (wid & 3) * 32;    // warp code base within 128

    const int pos0 = blockIdx.y * 128;
    const int K0   = blockIdx.x * 128;

    const uint32_t sbase = smem_to_u32(smbuf);

    const int srow = t >> 1;
    const int sseg = (t & 1) * 32;
    const char* zsrc = (const char*)(g_zbf + (size_t)(pos0 + srow) * 256) + sseg;
    const char* wsrc = (const char*)(g_wbf + (size_t)(K0 + srow) * 256) + sseg;
    const uint32_t zdst = sbase + srow * ZPITCHB + sseg;
    const uint32_t wdst = sbase + 20480u + srow * ZPITCHB + sseg;

    const int lrow16 = lane & 15;
    const int lcol8  = (lane >> 4) << 3;
    const int q      = lane >> 3;
    const int brow   = ((q >> 1) << 3) + (lane & 7);
    const int bk8    = (q & 1) << 3;

    float acc[4][4][4];
    #pragma unroll
    for (int f = 0; f < 4; ++f)
        #pragma unroll
        for (int n = 0; n < 4; ++n)
            #pragma unroll
            for (int e = 0; e < 4; ++e) acc[f][n][e] = 0.f;

    CP_ASYNC16(zdst, zsrc);
    CP_ASYNC16(zdst + 16, zsrc + 16);
    CP_ASYNC16(wdst, wsrc);
    CP_ASYNC16(wdst + 16, wsrc + 16);
    CP_COMMIT();
    CP_WAIT0();
    __syncthreads();

    int p = 0;
    for (int ct = 0; ct < 8; ++ct) {
        if (ct < 7) {
            const uint32_t nb = (uint32_t)(p ^ 1) * 10240u;
            const int coff = (ct + 1) * 64;
            CP_ASYNC16(zdst + nb, zsrc + coff);
            CP_ASYNC16(zdst + nb + 16, zsrc + coff + 16);
            CP_ASYNC16(wdst + nb, wsrc + coff);
            CP_ASYNC16(wdst + nb + 16, wsrc + coff + 16);
            CP_COMMIT();
        }
        const uint32_t zb = sbase + (uint32_t)p * 10240u;
        const uint32_t wb = sbase + 20480u + (uint32_t)p * 10240u;
        #pragma unroll
        for (int s = 0; s < 2; ++s) {
            uint32_t af[4][4];
            #pragma unroll
            for (int f = 0; f < 4; ++f) {
                uint32_t addr = zb + (uint32_t)(py * 64 + f * 16 + lrow16) * ZPITCHB
                              + (uint32_t)(s * 16 + lcol8) * 2u;
                LDSM4(af[f], addr);
            }
            uint32_t bf[4][2];
            #pragma unroll
            for (int nb2 = 0; nb2 < 2; ++nb2) {
                uint32_t r[4];
                uint32_t addr = wb + (uint32_t)(kb + nb2 * 16 + brow) * ZPITCHB
                              + (uint32_t)(s * 16 + bk8) * 2u;
                LDSM4(r, addr);
                bf[nb2 * 2][0] = r[0]; bf[nb2 * 2][1] = r[1];
                bf[nb2 * 2 + 1][0] = r[2]; bf[nb2 * 2 + 1][1] = r[3];
            }
            #pragma unroll
            for (int f = 0; f < 4; ++f)
                #pragma unroll
                for (int n = 0; n < 4; ++n)
                    MMA16816(acc[f][n], af[f], bf[n]);
        }
        if (ct < 7) {
            CP_WAIT0();
            __syncthreads();
            p ^= 1;
        }
    }
    __syncthreads();

    const int lr4 = lane >> 2;
    const int lc2 = (lane & 3) * 2;
    #pragma unroll
    for (int f = 0; f < 4; ++f) {
        const int r0 = py * 64 + f * 16 + lr4;
        #pragma unroll
        for (int n = 0; n < 4; ++n) {
            const int col = kb + n * 8 + lc2;
            float2 wq = *(const float2*)(g_wsq + K0 + col);
            uint32_t pk;
            float s0 = fmaf(-2.0f, acc[f][n][0], wq.x);
            float s1 = fmaf(-2.0f, acc[f][n][1], wq.y);
            CVTB(pk, s1, s0);
            *(uint32_t*)((char*)smbuf + (size_t)(r0 * SCPITCH + col) * 2) = pk;
            float s2 = fmaf(-2.0f, acc[f][n][2], wq.x);
            float s3 = fmaf(-2.0f, acc[f][n][3], wq.y);
            CVTB(pk, s3, s2);
            *(uint32_t*)((char*)smbuf + (size_t)((r0 + 8) * SCPITCH + col) * 2) = pk;
        }
    }
    __syncthreads();

    #pragma unroll
    for (int i = 0; i < 8; ++i) {
        int idx = t + i * 256;
        int row = idx >> 4, seg = idx & 15;
        uint4 v = *(const uint4*)((const char*)smbuf + (size_t)row * (SCPITCH * 2) + seg * 16);
        *(uint4*)((char*)(g_scores + (size_t)(pos0 + row) * 1024 + K0) + seg * 16) = v;
    }
}

// ---------------------------------------------------------------------------
// Kernel S: branch-free candidate flagging. Per position: warp min of approx
// scores, build per-lane 32-bit mask of candidates within MARGIN, append to
// global compacted list. Also init g_best.
// ---------------------------------------------------------------------------
__global__ __launch_bounds__(256) void k_scan() {
    const int t = threadIdx.x;
    const int wid = t >> 5, lane = t & 31;

    for (int pp = 0; pp < 4; ++pp) {
        const int pos = blockIdx.x * 32 + wid * 4 + pp;
        const uint4* srow = (const uint4*)(g_scores) + (size_t)pos * 128 + lane * 4;
        uint4 v[4];
        #pragma unroll
        for (int i = 0; i < 4; ++i) v[i] = srow[i];

        float mn = 3.4e38f;
        #pragma unroll
        for (int i = 0; i < 4; ++i) {
            const uint32_t* u = (const uint32_t*)&v[i];
            #pragma unroll
            for (int e = 0; e < 4; ++e) {
                float f0 = __uint_as_float(u[e] << 16);
                float f1 = __uint_as_float(u[e] & 0xFFFF0000u);
                mn = fminf(mn, fminf(f0, f1));
            }
        }
        #pragma unroll
        for (int off = 16; off > 0; off >>= 1)
            mn = fminf(mn, __shfl_xor_sync(0xFFFFFFFFu, mn, off));
        const float thr = mn + MARGIN;

        unsigned mask = 0u;
        #pragma unroll
        for (int i = 0; i < 4; ++i) {
            const uint32_t* u = (const uint32_t*)&v[i];
            #pragma unroll
            for (int e = 0; e < 4; ++e) {
                float f0 = __uint_as_float(u[e] << 16);
                float f1 = __uint_as_float(u[e] & 0xFFFF0000u);
                mask |= (f0 <= thr) ? (1u << (i * 8 + e * 2)) : 0u;
                mask |= (f1 <= thr) ? (1u << (i * 8 + e * 2 + 1)) : 0u;
            }
        }
        while (mask) {
            int bbit = __ffs(mask) - 1;
            mask &= mask - 1;
            unsigned k = (unsigned)(lane * 32 + bbit);
            unsigned slot = atomicAdd(&g_ncand, 1u);
            if (slot < CAND_CAP) g_cand[slot] = ((unsigned)pos << 10) | k;
        }
        if (lane == 0) g_best[pos] = ~0ull;
    }
}

// ---------------------------------------------------------------------------
// Kernel R: exact rescore of candidates. One thread per candidate; exact
// ascending-c fp32 FMA chain + reference dist rounding; order-preserving u64
// atomicMin (score hi, k lo -> lowest index wins ties).
// ---------------------------------------------------------------------------
__device__ __forceinline__ float chain256(const float* __restrict__ zr,
                                          const float* __restrict__ wr) {
    float m = 0.f;
    #pragma unroll 16
    for (int j = 0; j < 64; ++j) {
        float4 a = *(const float4*)(zr + 4 * j);
        float4 b = *(const float4*)(wr + 4 * j);
        m = fmaf(a.x, b.x, m);
        m = fmaf(a.y, b.y, m);
        m = fmaf(a.z, b.z, m);
        m = fmaf(a.w, b.w, m);
    }
    return m;
}

__global__ __launch_bounds__(256) void k_rescore(const float* __restrict__ w) {
    unsigned n = g_ncand;
    if (n > CAND_CAP) n = CAND_CAP;
    for (unsigned i = blockIdx.x * 256 + threadIdx.x; i < n; i += gridDim.x * 256) {
        const unsigned c = g_cand[i];
        const unsigned pos = c >> 10;
        const unsigned k = c & 1023u;
        float m = chain256(g_zt + (size_t)pos * CDIM, w + (size_t)k * CDIM);
        float sc = __fadd_rn(fmaf(-2.0f, m, g_zsq[pos]), g_wsq[k]);
        unsigned uu = __float_as_uint(sc);
        uu = (uu & 0x80000000u) ? ~uu : (uu | 0x80000000u);
        atomicMin(&g_best[pos], ((ull)uu << 32) | k);
    }
}

// ---------------------------------------------------------------------------
// Kernel B: gather-transpose quantize; decodes g_best, updates counts.
// ---------------------------------------------------------------------------
#define QPITCH 257
__global__ __launch_bounds__(256) void k_quant(const float* __restrict__ z,
                                               const float* __restrict__ w,
                                               float* __restrict__ out) {
    __shared__ int   sidx[32];
    __shared__ float qs[32 * QPITCH];
    __shared__ float sm[256];

    const int t  = threadIdx.x;
    const int n0 = blockIdx.x * 32;
    const int b  = n0 >> 10;
    const int hw0 = n0 & 1023;

    if (t < 32) {
        int idx = (int)(g_best[n0 + t] & 0xFFFFFFFFull);
        sidx[t] = idx;
        atomicAdd(&g_counts[idx], 1u);
    }
    __syncthreads();

    {
        const int p  = t >> 3;
        const int cq = t & 7;
        const float* row = w + (size_t)sidx[p] * CDIM;
        #pragma unroll
        for (int i = 0; i < 8; ++i) {
            const int c4 = (i * 8 + cq) * 4;
            float4 v = *(const float4*)(row + c4);
            float* dst = &qs[p * QPITCH + c4];
            dst[0] = v.x; dst[1] = v.y; dst[2] = v.z; dst[3] = v.w;
        }
    }
    __syncthreads();

    const float* zb = z + (size_t)b * (CDIM * HW) + hw0;
    float* ob = out + (size_t)b * (CDIM * HW) + hw0;
    const int hw4 = (t & 7) * 4;
    float local = 0.f;
    #pragma unroll
    for (int it = 0; it < 8; ++it) {
        const int c = it * 32 + (t >> 3);
        float4 zz = *(const float4*)(zb + (size_t)c * HW + hw4);
        float q0 = qs[(hw4 + 0) * QPITCH + c];
        float q1 = qs[(hw4 + 1) * QPITCH + c];
        float q2 = qs[(hw4 + 2) * QPITCH + c];
        float q3 = qs[(hw4 + 3) * QPITCH + c];
        float4 o;
        float d;
        d = __fadd_rn(q0, -zz.x); o.x = __fadd_rn(zz.x, d); local = fmaf(d, d, local);
        d = __fadd_rn(q1, -zz.y); o.y = __fadd_rn(zz.y, d); local = fmaf(d, d, local);
        d = __fadd_rn(q2, -zz.z); o.z = __fadd_rn(zz.z, d); local = fmaf(d, d, local);
        d = __fadd_rn(q3, -zz.w); o.w = __fadd_rn(zz.w, d); local = fmaf(d, d, local);
        *(float4*)(ob + (size_t)c * HW + hw4) = o;
    }
    sm[t] = local;
    __syncthreads();
    for (int s = 128; s > 0; s >>= 1) {
        if (t < s) sm[t] += sm[t + s];
        __syncthreads();
    }
    if (t == 0) g_partial[blockIdx.x] = sm[0];
}

// ---------------------------------------------------------------------------
__global__ __launch_bounds__(1024) void k_final(float* __restrict__ out) {
    __shared__ float sm[1024];
    const int t = threadIdx.x;

    sm[t] = g_partial[t];
    __syncthreads();
    for (int s = 512; s > 0; s >>= 1) {
        if (t < s) sm[t] += sm[t + s];
        __syncthreads();
    }
    if (t == 0) {
        float m = sm[0] / (float)TOTAL;
        out[TOTAL] = m + 0.25f * m;      // q_latent + COMMITMENT_COST * e_latent
    }
    __syncthreads();

    float p = (float)g_counts[t] * (1.0f / (float)NPOS);
    sm[t] = p * logf(p + 1e-10f);
    __syncthreads();
    for (int s = 512; s > 0; s >>= 1) {
        if (t < s) sm[t] += sm[t + s];
        __syncthreads();
    }
    if (t == 0) out[TOTAL + 1] = expf(-sm[0]);
}

// ---------------------------------------------------------------------------
extern "C" void kernel_launch(void* const* d_in, const int* in_sizes, int n_in,
                              void* d_out, int out_size) {
    const float* z = (const float*)d_in[0];
    const float* w = (const float*)d_in[1];
    float* out = (float*)d_out;

    k_wsq<<<128, 256>>>(w);
    k_prep<<<NPOS / 32, 256>>>(z);
    k_gemm<<<dim3(8, 256), 256>>>();
    k_scan<<<NPOS / 32, 256>>>();
    k_rescore<<<256, 256>>>(w);
    k_quant<<<NPOS / 32, 256>>>(z, w, out);
    k_final<<<1, 1024>>>(out);
}